// round 1
// baseline (speedup 1.0000x reference)
#include <cuda_runtime.h>
#include <cuda_bf16.h>

#define NDIR_MAX 1024
#define WARPS_PER_BLOCK 8
#define NTHREADS (WARPS_PER_BLOCK * 32)

// fast 2^x via round-to-nearest magic + degree-5 Taylor on [-0.5,0.5]
// rel err ~2e-6 over |x| <= 126
__device__ __forceinline__ float fexp2(float x) {
    x = fminf(fmaxf(x, -126.0f), 126.0f);
    float t = x + 12582912.0f;                 // 1.5*2^23: RN to integer
    float r = x - (t - 12582912.0f);           // r in [-0.5, 0.5]
    int   ni = __float_as_int(t) - 0x4B400000; // integer part
    float p =            1.3333558e-3f;
    p = fmaf(p, r, 9.6181291e-3f);
    p = fmaf(p, r, 5.5504109e-2f);
    p = fmaf(p, r, 2.4022651e-1f);
    p = fmaf(p, r, 6.9314718e-1f);
    p = fmaf(p, r, 1.0f);
    return p * __int_as_float((ni + 127) << 23);
}

__global__ __launch_bounds__(NTHREADS)
void closure_kernel(const float* __restrict__ F4,
                    const float* __restrict__ gdx,
                    const float* __restrict__ gdy,
                    const float* __restrict__ gdz,
                    const float* __restrict__ gqw,
                    float* __restrict__ out,
                    int B, int nd)
{
    __shared__ float4 s_dir[NDIR_MAX];
    for (int j = threadIdx.x; j < nd; j += NTHREADS)
        s_dir[j] = make_float4(gdx[j], gdy[j], gdz[j], gqw[j]);
    __syncthreads();

    const int warp = threadIdx.x >> 5;
    const int lane = threadIdx.x & 31;
    const int b = blockIdx.x * WARPS_PER_BLOCK + warp;
    if (b >= B) return;

    const float EPS    = 1e-12f;
    const float INV4PI = 0.07957747154594767f;
    const float LOG2E  = 1.4426950408889634f;

    const float* in = F4 + (size_t)b * 24;

    // species: 0=e, 1=ebar, 2=x, 3=xbar
    float Fx[4], Fy[4], Fz[4], Ns[4];
    Fx[0] = in[0];  Fy[0] = in[1];  Fz[0] = in[2];  Ns[0] = in[3];
    Fx[1] = in[12]; Fy[1] = in[13]; Fz[1] = in[14]; Ns[1] = in[15];
    Fx[2] = 0.5f*(in[4]  + in[8]);  Fy[2] = 0.5f*(in[5]  + in[9]);
    Fz[2] = 0.5f*(in[6]  + in[10]); Ns[2] = 0.5f*(in[7]  + in[11]);
    Fx[3] = 0.5f*(in[16] + in[20]); Fy[3] = 0.5f*(in[17] + in[21]);
    Fz[3] = 0.5f*(in[18] + in[22]); Ns[3] = 0.5f*(in[19] + in[23]);

    float A[4], Kx[4], Ky[4], Kz[4];
    #pragma unroll
    for (int s = 0; s < 4; s++) {
        float N   = fmaxf(Ns[s], EPS);
        float nrm = sqrtf(Fx[s]*Fx[s] + Fy[s]*Fy[s] + Fz[s]*Fz[s]);
        float f   = fminf(fmaxf(nrm / N, 0.0f), 0.999999f);
        float f2 = f*f, f4 = f2*f2, f6 = f4*f2, f8 = f4*f4;
        float denom = 3.0f - 1.00651f*f2 - 0.962251f*f4 + 1.47353f*f6 - 0.48953f*f8;
        denom = fmaxf(denom, EPS);
        float p = 1.0f - 2.0f*(1.0f - f)*(1.0f + 1.01524f*f) / denom;
        float Z = 2.0f*f / fmaxf(1.0f - p, 1e-6f);
        // z / sinh(z)
        float zsz;
        if (fabsf(Z) < 1e-4f) {
            float z2 = Z*Z;
            zsz = 1.0f - z2*(1.0f/6.0f) + z2*z2*(1.0f/120.0f);
        } else {
            float E  = fexp2(Z * LOG2E);
            float sh = 0.5f * (E - 1.0f/E);
            zsz = Z / sh;
        }
        A[s] = N * INV4PI * zsz;
        float scl = (Z / fmaxf(nrm, EPS)) * LOG2E;
        Kx[s] = Fx[s]*scl; Ky[s] = Fy[s]*scl; Kz[s] = Fz[s]*scl;
    }

    // 24 accumulators: [s*4+k] totals of w*g_s*{1,dx,dy,dz};
    // [16+k] = sum_{delta>=0} w*u*{...}; [20+k] = sum_{delta>=0} w*v*{...}
    float acc[24];
    #pragma unroll
    for (int i = 0; i < 24; i++) acc[i] = 0.0f;

    for (int d = lane; d < nd; d += 32) {
        float4 q = s_dir[d];
        float g0 = A[0] * fexp2(fmaf(Kx[0], q.x, fmaf(Ky[0], q.y, Kz[0]*q.z)));
        float g1 = A[1] * fexp2(fmaf(Kx[1], q.x, fmaf(Ky[1], q.y, Kz[1]*q.z)));
        float g2 = A[2] * fexp2(fmaf(Kx[2], q.x, fmaf(Ky[2], q.y, Kz[2]*q.z)));
        float g3 = A[3] * fexp2(fmaf(Kx[3], q.x, fmaf(Ky[3], q.y, Kz[3]*q.z)));
        float w = q.w;
        float wg0 = w*g0, wg1 = w*g1, wg2 = w*g2, wg3 = w*g3;

        acc[0]  += wg0; acc[1]  = fmaf(wg0, q.x, acc[1]);  acc[2]  = fmaf(wg0, q.y, acc[2]);  acc[3]  = fmaf(wg0, q.z, acc[3]);
        acc[4]  += wg1; acc[5]  = fmaf(wg1, q.x, acc[5]);  acc[6]  = fmaf(wg1, q.y, acc[6]);  acc[7]  = fmaf(wg1, q.z, acc[7]);
        acc[8]  += wg2; acc[9]  = fmaf(wg2, q.x, acc[9]);  acc[10] = fmaf(wg2, q.y, acc[10]); acc[11] = fmaf(wg2, q.z, acc[11]);
        acc[12] += wg3; acc[13] = fmaf(wg3, q.x, acc[13]); acc[14] = fmaf(wg3, q.y, acc[14]); acc[15] = fmaf(wg3, q.z, acc[15]);

        float wu = wg0 - wg2;     // w*(g0-g2)
        float wv = wg1 - wg3;     // w*(g1-g3)
        if (wu >= wv) {           // delta = u - v >= 0 (w > 0)
            acc[16] += wu; acc[17] = fmaf(wu, q.x, acc[17]); acc[18] = fmaf(wu, q.y, acc[18]); acc[19] = fmaf(wu, q.z, acc[19]);
            acc[20] += wv; acc[21] = fmaf(wv, q.x, acc[21]); acc[22] = fmaf(wv, q.y, acc[22]); acc[23] = fmaf(wv, q.z, acc[23]);
        }
    }

    // butterfly reduction: every lane ends with all 24 totals
    #pragma unroll
    for (int off = 16; off > 0; off >>= 1) {
        #pragma unroll
        for (int i = 0; i < 24; i++)
            acc[i] += __shfl_xor_sync(0xffffffffu, acc[i], off);
    }

    float Su[4], Sv[4];
    #pragma unroll
    for (int k = 0; k < 4; k++) {
        Su[k] = acc[0 + k] - acc[8 + k];   // total sum w*u*{...}
        Sv[k] = acc[4 + k] - acc[12 + k];  // total sum w*v*{...}
    }
    float Iplus  = acc[16] - acc[20];
    float Iminus = (Sv[0] - acc[20]) - (Su[0] - acc[16]);
    float Ips = fmaxf(Iplus,  EPS);
    float Ims = fmaxf(Iminus, EPS);
    float cp, cn;
    if (Iplus < Iminus) {
        cp = 1.0f / 3.0f;
        cn = fminf(fmaxf(1.0f - (2.0f/3.0f)*(Ips/Ims), 0.0f), 1.0f);
    } else {
        cn = 1.0f / 3.0f;
        cp = fminf(fmaxf(1.0f - (2.0f/3.0f)*(Ims/Ips), 0.0f), 1.0f);
    }
    float growth = sqrtf(fmaxf(Iplus * Iminus, 0.0f));

    float n0[4], n1[4], n2[4], n3[4];
    #pragma unroll
    for (int k = 0; k < 4; k++) {
        float Pu = cp*acc[16 + k] + cn*(Su[k] - acc[16 + k]);  // sum w*Psur*u
        float Pv = cp*acc[20 + k] + cn*(Sv[k] - acc[20 + k]);  // sum w*Psur*v
        n0[k] = acc[8 + k]  + Pu;                               // e
        n1[k] = acc[12 + k] + Pv;                               // ebar
        n2[k] = 0.5f*(acc[0 + k] + acc[8 + k])  - 0.5f*Pu;      // x
        n3[k] = 0.5f*(acc[4 + k] + acc[12 + k]) - 0.5f*Pv;      // xbar
    }

    // F4mix layout (B,2,3,4): channel order [Fx,Fy,Fz,N]
    float4* ob = (float4*)(out + (size_t)b * 24);
    if (lane == 0) ob[0] = make_float4(n0[1], n0[2], n0[3], n0[0]); // i=0,f=0  (e)
    if (lane == 1) ob[1] = make_float4(n2[1], n2[2], n2[3], n2[0]); // i=0,f=1  (x)
    if (lane == 2) ob[2] = make_float4(n2[1], n2[2], n2[3], n2[0]); // i=0,f=2  (x)
    if (lane == 3) ob[3] = make_float4(n1[1], n1[2], n1[3], n1[0]); // i=1,f=0  (ebar)
    if (lane == 4) ob[4] = make_float4(n3[1], n3[2], n3[3], n3[0]); // i=1,f=1  (xbar)
    if (lane == 5) ob[5] = make_float4(n3[1], n3[2], n3[3], n3[0]); // i=1,f=2  (xbar)
    if (lane == 6) out[(size_t)B * 24 + b] = growth;
}

extern "C" void kernel_launch(void* const* d_in, const int* in_sizes, int n_in,
                              void* d_out, int out_size) {
    const float* F4  = (const float*)d_in[0];
    const float* ddx = (const float*)d_in[1];
    const float* ddy = (const float*)d_in[2];
    const float* ddz = (const float*)d_in[3];
    const float* dqw = (const float*)d_in[4];
    float* out = (float*)d_out;

    int B  = in_sizes[0] / 24;
    int nd = in_sizes[1];

    int grid = (B + WARPS_PER_BLOCK - 1) / WARPS_PER_BLOCK;
    closure_kernel<<<grid, NTHREADS>>>(F4, ddx, ddy, ddz, dqw, out, B, nd);
}

// round 2
// speedup vs baseline: 1.0019x; 1.0019x over previous
#include <cuda_runtime.h>
#include <cuda_bf16.h>

#define NDIR_MAX 1024
#define WARPS_PER_BLOCK 8
#define NTHREADS (WARPS_PER_BLOCK * 32)

typedef unsigned long long u64;

// ---- packed f32x2 helpers (Blackwell FFMA2 path — PTX-only) ----
__device__ __forceinline__ u64 pk(float lo, float hi) {
    u64 r; asm("mov.b64 %0, {%1, %2};" : "=l"(r) : "f"(lo), "f"(hi)); return r;
}
__device__ __forceinline__ void upk(float& lo, float& hi, u64 v) {
    asm("mov.b64 {%0, %1}, %2;" : "=f"(lo), "=f"(hi) : "l"(v));
}
__device__ __forceinline__ u64 f2fma(u64 a, u64 b, u64 c) {
    u64 d; asm("fma.rn.f32x2 %0, %1, %2, %3;" : "=l"(d) : "l"(a), "l"(b), "l"(c)); return d;
}
__device__ __forceinline__ u64 f2mul(u64 a, u64 b) {
    u64 d; asm("mul.rn.f32x2 %0, %1, %2;" : "=l"(d) : "l"(a), "l"(b)); return d;
}
__device__ __forceinline__ u64 f2add(u64 a, u64 b) {
    u64 d; asm("add.rn.f32x2 %0, %1, %2;" : "=l"(d) : "l"(a), "l"(b)); return d;
}
__device__ __forceinline__ float fex2(float x) {   // MUFU pipe
    float r; asm("ex2.approx.f32 %0, %1;" : "=f"(r) : "f"(x)); return r;
}

__global__ __launch_bounds__(NTHREADS)
void closure_kernel(const float* __restrict__ F4,
                    const float* __restrict__ gdx,
                    const float* __restrict__ gdy,
                    const float* __restrict__ gdz,
                    const float* __restrict__ gqw,
                    float* __restrict__ out,
                    int B, int nd)
{
    __shared__ float4 s_dir[NDIR_MAX];
    for (int j = threadIdx.x; j < nd; j += NTHREADS)
        s_dir[j] = make_float4(gdx[j], gdy[j], gdz[j], gqw[j]);
    if (threadIdx.x == 0 && nd < NDIR_MAX)
        s_dir[nd] = make_float4(0.f, 0.f, 0.f, 0.f);   // pad for odd nd
    __syncthreads();

    const int warp = threadIdx.x >> 5;
    const int lane = threadIdx.x & 31;
    const int b = blockIdx.x * WARPS_PER_BLOCK + warp;
    if (b >= B) return;

    const float EPS    = 1e-12f;
    const float INV4PI = 0.07957747154594767f;
    const float LOG2E  = 1.4426950408889634f;

    const float* in = F4 + (size_t)b * 24;

    // species: 0=e, 1=ebar, 2=x, 3=xbar
    float Fx[4], Fy[4], Fz[4], Ns[4];
    Fx[0] = in[0];  Fy[0] = in[1];  Fz[0] = in[2];  Ns[0] = in[3];
    Fx[1] = in[12]; Fy[1] = in[13]; Fz[1] = in[14]; Ns[1] = in[15];
    Fx[2] = 0.5f*(in[4]  + in[8]);  Fy[2] = 0.5f*(in[5]  + in[9]);
    Fz[2] = 0.5f*(in[6]  + in[10]); Ns[2] = 0.5f*(in[7]  + in[11]);
    Fx[3] = 0.5f*(in[16] + in[20]); Fy[3] = 0.5f*(in[17] + in[21]);
    Fz[3] = 0.5f*(in[18] + in[22]); Ns[3] = 0.5f*(in[19] + in[23]);

    u64 Ap[4], Kxp[4], Kyp[4], Kzp[4];
    #pragma unroll
    for (int s = 0; s < 4; s++) {
        float N   = fmaxf(Ns[s], EPS);
        float nrm = sqrtf(Fx[s]*Fx[s] + Fy[s]*Fy[s] + Fz[s]*Fz[s]);
        float f   = fminf(fmaxf(nrm / N, 0.0f), 0.999999f);
        float f2 = f*f, f4 = f2*f2, f6 = f4*f2, f8 = f4*f4;
        float denom = 3.0f - 1.00651f*f2 - 0.962251f*f4 + 1.47353f*f6 - 0.48953f*f8;
        denom = fmaxf(denom, EPS);
        float p = 1.0f - 2.0f*(1.0f - f)*(1.0f + 1.01524f*f) / denom;
        float Z = 2.0f*f / fmaxf(1.0f - p, 1e-6f);
        Z = fminf(Z, 85.0f);                       // |exp arg| bounded: |mu|<=1
        // z / sinh(z)
        float zsz;
        if (fabsf(Z) < 1e-4f) {
            float z2 = Z*Z;
            zsz = 1.0f - z2*(1.0f/6.0f) + z2*z2*(1.0f/120.0f);
        } else {
            float E  = fex2(Z * LOG2E);
            float sh = 0.5f * (E - 1.0f/E);
            zsz = Z / sh;
        }
        float A = N * INV4PI * zsz;
        float scl = (Z / fmaxf(nrm, EPS)) * LOG2E;  // fold log2(e) into K
        Ap[s]  = pk(A, A);
        Kxp[s] = pk(Fx[s]*scl, Fx[s]*scl);
        Kyp[s] = pk(Fy[s]*scl, Fy[s]*scl);
        Kzp[s] = pk(Fz[s]*scl, Fz[s]*scl);
    }

    // 24 packed accumulators (each holds partial sums for 2 dirs)
    u64 acc[24];
    #pragma unroll
    for (int i = 0; i < 24; i++) acc[i] = 0ull;

    const int npair = (nd + 1) >> 1;
    for (int p = lane; p < npair; p += 32) {
        float4 qa = s_dir[2*p];
        float4 qb = s_dir[2*p + 1];
        u64 qx = pk(qa.x, qb.x);
        u64 qy = pk(qa.y, qb.y);
        u64 qz = pk(qa.z, qb.z);
        u64 qw = pk(qa.w, qb.w);

        // exp args (K pre-scaled by log2 e) — packed dot products
        u64 m0 = f2fma(Kxp[0], qx, f2fma(Kyp[0], qy, f2mul(Kzp[0], qz)));
        u64 m1 = f2fma(Kxp[1], qx, f2fma(Kyp[1], qy, f2mul(Kzp[1], qz)));
        u64 m2 = f2fma(Kxp[2], qx, f2fma(Kyp[2], qy, f2mul(Kzp[2], qz)));
        u64 m3 = f2fma(Kxp[3], qx, f2fma(Kyp[3], qy, f2mul(Kzp[3], qz)));

        // exponentials on the MUFU pipe (scalar halves)
        float a0,b0,a1,b1,a2,b2,a3,b3;
        upk(a0,b0,m0); upk(a1,b1,m1); upk(a2,b2,m2); upk(a3,b3,m3);
        u64 g0 = f2mul(Ap[0], pk(fex2(a0), fex2(b0)));
        u64 g1 = f2mul(Ap[1], pk(fex2(a1), fex2(b1)));
        u64 g2 = f2mul(Ap[2], pk(fex2(a2), fex2(b2)));
        u64 g3 = f2mul(Ap[3], pk(fex2(a3), fex2(b3)));

        u64 wg0 = f2mul(qw, g0);
        u64 wg1 = f2mul(qw, g1);
        u64 wg2 = f2mul(qw, g2);
        u64 wg3 = f2mul(qw, g3);

        acc[0]  = f2add(acc[0],  wg0); acc[1]  = f2fma(wg0, qx, acc[1]);
        acc[2]  = f2fma(wg0, qy, acc[2]);  acc[3]  = f2fma(wg0, qz, acc[3]);
        acc[4]  = f2add(acc[4],  wg1); acc[5]  = f2fma(wg1, qx, acc[5]);
        acc[6]  = f2fma(wg1, qy, acc[6]);  acc[7]  = f2fma(wg1, qz, acc[7]);
        acc[8]  = f2add(acc[8],  wg2); acc[9]  = f2fma(wg2, qx, acc[9]);
        acc[10] = f2fma(wg2, qy, acc[10]); acc[11] = f2fma(wg2, qz, acc[11]);
        acc[12] = f2add(acc[12], wg3); acc[13] = f2fma(wg3, qx, acc[13]);
        acc[14] = f2fma(wg3, qy, acc[14]); acc[15] = f2fma(wg3, qz, acc[15]);

        // wu = w*(g0-g2), wv = w*(g1-g3); bucket where delta = wu-wv >= 0
        const u64 NEG1 = 0xBF800000BF800000ull;    // (-1.f, -1.f)
        u64 wu = f2fma(wg2, NEG1, wg0);
        u64 wv = f2fma(wg3, NEG1, wg1);
        float wua,wub,wva,wvb;
        upk(wua, wub, wu);
        upk(wva, wvb, wv);
        bool ca = (wua >= wva), cb = (wub >= wvb);
        u64 mu = pk(ca ? wua : 0.0f, cb ? wub : 0.0f);
        u64 mv = pk(ca ? wva : 0.0f, cb ? wvb : 0.0f);

        acc[16] = f2add(acc[16], mu); acc[17] = f2fma(mu, qx, acc[17]);
        acc[18] = f2fma(mu, qy, acc[18]); acc[19] = f2fma(mu, qz, acc[19]);
        acc[20] = f2add(acc[20], mv); acc[21] = f2fma(mv, qx, acc[21]);
        acc[22] = f2fma(mv, qy, acc[22]); acc[23] = f2fma(mv, qz, acc[23]);
    }

    // collapse packs to scalars, then butterfly-reduce across the warp
    float r[24];
    #pragma unroll
    for (int i = 0; i < 24; i++) {
        float lo, hi; upk(lo, hi, acc[i]);
        r[i] = lo + hi;
    }
    #pragma unroll
    for (int off = 16; off > 0; off >>= 1) {
        #pragma unroll
        for (int i = 0; i < 24; i++)
            r[i] += __shfl_xor_sync(0xffffffffu, r[i], off);
    }

    float Su[4], Sv[4];
    #pragma unroll
    for (int k = 0; k < 4; k++) {
        Su[k] = r[0 + k] - r[8 + k];   // total  sum w*u*{1,x,y,z}
        Sv[k] = r[4 + k] - r[12 + k];  // total  sum w*v*{1,x,y,z}
    }
    float Iplus  = r[16] - r[20];
    float Iminus = (Sv[0] - r[20]) - (Su[0] - r[16]);
    float Ips = fmaxf(Iplus,  EPS);
    float Ims = fmaxf(Iminus, EPS);
    float cp, cn;
    if (Iplus < Iminus) {
        cp = 1.0f / 3.0f;
        cn = fminf(fmaxf(1.0f - (2.0f/3.0f)*(Ips/Ims), 0.0f), 1.0f);
    } else {
        cn = 1.0f / 3.0f;
        cp = fminf(fmaxf(1.0f - (2.0f/3.0f)*(Ims/Ips), 0.0f), 1.0f);
    }
    float growth = sqrtf(fmaxf(Iplus * Iminus, 0.0f));

    float n0[4], n1[4], n2[4], n3[4];
    #pragma unroll
    for (int k = 0; k < 4; k++) {
        float Pu = cp*r[16 + k] + cn*(Su[k] - r[16 + k]);  // sum w*Psur*u
        float Pv = cp*r[20 + k] + cn*(Sv[k] - r[20 + k]);  // sum w*Psur*v
        n0[k] = r[8 + k]  + Pu;                            // e
        n1[k] = r[12 + k] + Pv;                            // ebar
        n2[k] = 0.5f*(r[0 + k] + r[8 + k])  - 0.5f*Pu;     // x
        n3[k] = 0.5f*(r[4 + k] + r[12 + k]) - 0.5f*Pv;     // xbar
    }

    // F4mix layout (B,2,3,4): channel order [Fx,Fy,Fz,N]
    float4* ob = (float4*)(out + (size_t)b * 24);
    if (lane == 0) ob[0] = make_float4(n0[1], n0[2], n0[3], n0[0]); // i=0,f=0 (e)
    if (lane == 1) ob[1] = make_float4(n2[1], n2[2], n2[3], n2[0]); // i=0,f=1 (x)
    if (lane == 2) ob[2] = make_float4(n2[1], n2[2], n2[3], n2[0]); // i=0,f=2 (x)
    if (lane == 3) ob[3] = make_float4(n1[1], n1[2], n1[3], n1[0]); // i=1,f=0 (ebar)
    if (lane == 4) ob[4] = make_float4(n3[1], n3[2], n3[3], n3[0]); // i=1,f=1 (xbar)
    if (lane == 5) ob[5] = make_float4(n3[1], n3[2], n3[3], n3[0]); // i=1,f=2 (xbar)
    if (lane == 6) out[(size_t)B * 24 + b] = growth;
}

extern "C" void kernel_launch(void* const* d_in, const int* in_sizes, int n_in,
                              void* d_out, int out_size) {
    const float* F4  = (const float*)d_in[0];
    const float* ddx = (const float*)d_in[1];
    const float* ddy = (const float*)d_in[2];
    const float* ddz = (const float*)d_in[3];
    const float* dqw = (const float*)d_in[4];
    float* out = (float*)d_out;

    int B  = in_sizes[0] / 24;
    int nd = in_sizes[1];

    int grid = (B + WARPS_PER_BLOCK - 1) / WARPS_PER_BLOCK;
    closure_kernel<<<grid, NTHREADS>>>(F4, ddx, ddy, ddz, dqw, out, B, nd);
}

// round 3
// speedup vs baseline: 1.3027x; 1.3002x over previous
#include <cuda_runtime.h>
#include <cuda_bf16.h>

#define NDIR_MAX 1024
#define WARPS_PER_BLOCK 8
#define NTHREADS (WARPS_PER_BLOCK * 32)

__device__ __forceinline__ float fex2(float x) {   // MUFU pipe: 2^x
    float r; asm("ex2.approx.f32 %0, %1;" : "=f"(r) : "f"(x)); return r;
}
__device__ __forceinline__ float flg2(float x) {   // MUFU pipe: log2(x)
    float r; asm("lg2.approx.f32 %0, %1;" : "=f"(r) : "f"(x)); return r;
}

__global__ __launch_bounds__(NTHREADS)
void closure_kernel(const float* __restrict__ F4,
                    const float* __restrict__ gdx,
                    const float* __restrict__ gdy,
                    const float* __restrict__ gdz,
                    const float* __restrict__ gqw,
                    float* __restrict__ out,
                    int B, int nd)
{
    __shared__ float4 s_dir[NDIR_MAX];
    for (int j = threadIdx.x; j < nd; j += NTHREADS)
        s_dir[j] = make_float4(gdx[j], gdy[j], gdz[j], gqw[j]);
    __syncthreads();

    const int warp = threadIdx.x >> 5;
    const int lane = threadIdx.x & 31;
    const int b = blockIdx.x * WARPS_PER_BLOCK + warp;
    if (b >= B) return;

    const float EPS    = 1e-12f;
    const float INV4PI = 0.07957747154594767f;
    const float LOG2E  = 1.4426950408889634f;

    const float* in = F4 + (size_t)b * 24;

    // species: 0=e, 1=ebar, 2=x, 3=xbar
    float Fx[4], Fy[4], Fz[4], Ns[4];
    Fx[0] = in[0];  Fy[0] = in[1];  Fz[0] = in[2];  Ns[0] = in[3];
    Fx[1] = in[12]; Fy[1] = in[13]; Fz[1] = in[14]; Ns[1] = in[15];
    Fx[2] = 0.5f*(in[4]  + in[8]);  Fy[2] = 0.5f*(in[5]  + in[9]);
    Fz[2] = 0.5f*(in[6]  + in[10]); Ns[2] = 0.5f*(in[7]  + in[11]);
    Fx[3] = 0.5f*(in[16] + in[20]); Fy[3] = 0.5f*(in[17] + in[21]);
    Fz[3] = 0.5f*(in[18] + in[22]); Ns[3] = 0.5f*(in[19] + in[23]);

    float La[4], Kx[4], Ky[4], Kz[4];
    #pragma unroll
    for (int s = 0; s < 4; s++) {
        float N   = fmaxf(Ns[s], EPS);
        float nrm = sqrtf(Fx[s]*Fx[s] + Fy[s]*Fy[s] + Fz[s]*Fz[s]);
        float f   = fminf(fmaxf(nrm / N, 0.0f), 0.999999f);
        float f2 = f*f, f4 = f2*f2, f6 = f4*f2, f8 = f4*f4;
        float denom = 3.0f - 1.00651f*f2 - 0.962251f*f4 + 1.47353f*f6 - 0.48953f*f8;
        denom = fmaxf(denom, EPS);
        float p = 1.0f - 2.0f*(1.0f - f)*(1.0f + 1.01524f*f) / denom;
        float Z = 2.0f*f / fmaxf(1.0f - p, 1e-6f);
        Z = fminf(Z, 85.0f);
        // z / sinh(z)
        float zsz;
        if (fabsf(Z) < 1e-4f) {
            float z2 = Z*Z;
            zsz = 1.0f - z2*(1.0f/6.0f) + z2*z2*(1.0f/120.0f);
        } else {
            float E  = fex2(Z * LOG2E);
            float sh = 0.5f * (E - 1.0f/E);
            zsz = Z / sh;
        }
        float A = N * INV4PI * zsz;          // A > 0 always
        La[s] = flg2(A);                     // fold amplitude into exponent
        float scl = (Z / fmaxf(nrm, EPS)) * LOG2E;
        Kx[s] = Fx[s]*scl; Ky[s] = Fy[s]*scl; Kz[s] = Fz[s]*scl;
    }

    // 24 accumulators: [s*4+k] totals of w*g_s*{1,dx,dy,dz};
    // [16+k] = sum_{delta>=0} w*u*{...}; [20+k] = sum_{delta>=0} w*v*{...}
    float acc[24];
    #pragma unroll
    for (int i = 0; i < 24; i++) acc[i] = 0.0f;

    #pragma unroll 5
    for (int d = lane; d < nd; d += 32) {
        float4 q = s_dir[d];
        float g0 = fex2(fmaf(Kx[0], q.x, fmaf(Ky[0], q.y, fmaf(Kz[0], q.z, La[0]))));
        float g1 = fex2(fmaf(Kx[1], q.x, fmaf(Ky[1], q.y, fmaf(Kz[1], q.z, La[1]))));
        float g2 = fex2(fmaf(Kx[2], q.x, fmaf(Ky[2], q.y, fmaf(Kz[2], q.z, La[2]))));
        float g3 = fex2(fmaf(Kx[3], q.x, fmaf(Ky[3], q.y, fmaf(Kz[3], q.z, La[3]))));
        float w = q.w;
        float wg0 = w*g0, wg1 = w*g1, wg2 = w*g2, wg3 = w*g3;

        acc[0]  += wg0; acc[1]  = fmaf(wg0, q.x, acc[1]);  acc[2]  = fmaf(wg0, q.y, acc[2]);  acc[3]  = fmaf(wg0, q.z, acc[3]);
        acc[4]  += wg1; acc[5]  = fmaf(wg1, q.x, acc[5]);  acc[6]  = fmaf(wg1, q.y, acc[6]);  acc[7]  = fmaf(wg1, q.z, acc[7]);
        acc[8]  += wg2; acc[9]  = fmaf(wg2, q.x, acc[9]);  acc[10] = fmaf(wg2, q.y, acc[10]); acc[11] = fmaf(wg2, q.z, acc[11]);
        acc[12] += wg3; acc[13] = fmaf(wg3, q.x, acc[13]); acc[14] = fmaf(wg3, q.y, acc[14]); acc[15] = fmaf(wg3, q.z, acc[15]);

        float wu = wg0 - wg2;     // w*(g0-g2)
        float wv = wg1 - wg3;     // w*(g1-g3)
        if (wu >= wv) {           // delta >= 0 (w > 0)
            acc[16] += wu; acc[17] = fmaf(wu, q.x, acc[17]); acc[18] = fmaf(wu, q.y, acc[18]); acc[19] = fmaf(wu, q.z, acc[19]);
            acc[20] += wv; acc[21] = fmaf(wv, q.x, acc[21]); acc[22] = fmaf(wv, q.y, acc[22]); acc[23] = fmaf(wv, q.z, acc[23]);
        }
    }

    // butterfly reduction: every lane ends with all 24 totals
    #pragma unroll
    for (int off = 16; off > 0; off >>= 1) {
        #pragma unroll
        for (int i = 0; i < 24; i++)
            acc[i] += __shfl_xor_sync(0xffffffffu, acc[i], off);
    }

    float Su[4], Sv[4];
    #pragma unroll
    for (int k = 0; k < 4; k++) {
        Su[k] = acc[0 + k] - acc[8 + k];   // total sum w*u*{1,x,y,z}
        Sv[k] = acc[4 + k] - acc[12 + k];  // total sum w*v*{1,x,y,z}
    }
    float Iplus  = acc[16] - acc[20];
    float Iminus = (Sv[0] - acc[20]) - (Su[0] - acc[16]);
    float Ips = fmaxf(Iplus,  EPS);
    float Ims = fmaxf(Iminus, EPS);
    float cp, cn;
    if (Iplus < Iminus) {
        cp = 1.0f / 3.0f;
        cn = fminf(fmaxf(1.0f - (2.0f/3.0f)*(Ips/Ims), 0.0f), 1.0f);
    } else {
        cn = 1.0f / 3.0f;
        cp = fminf(fmaxf(1.0f - (2.0f/3.0f)*(Ims/Ips), 0.0f), 1.0f);
    }
    float growth = sqrtf(fmaxf(Iplus * Iminus, 0.0f));

    float n0[4], n1[4], n2[4], n3[4];
    #pragma unroll
    for (int k = 0; k < 4; k++) {
        float Pu = cp*acc[16 + k] + cn*(Su[k] - acc[16 + k]);  // sum w*Psur*u
        float Pv = cp*acc[20 + k] + cn*(Sv[k] - acc[20 + k]);  // sum w*Psur*v
        n0[k] = acc[8 + k]  + Pu;                               // e
        n1[k] = acc[12 + k] + Pv;                               // ebar
        n2[k] = 0.5f*(acc[0 + k] + acc[8 + k])  - 0.5f*Pu;      // x
        n3[k] = 0.5f*(acc[4 + k] + acc[12 + k]) - 0.5f*Pv;      // xbar
    }

    // F4mix layout (B,2,3,4): channel order [Fx,Fy,Fz,N]
    float4* ob = (float4*)(out + (size_t)b * 24);
    if (lane == 0) ob[0] = make_float4(n0[1], n0[2], n0[3], n0[0]); // i=0,f=0 (e)
    if (lane == 1) ob[1] = make_float4(n2[1], n2[2], n2[3], n2[0]); // i=0,f=1 (x)
    if (lane == 2) ob[2] = make_float4(n2[1], n2[2], n2[3], n2[0]); // i=0,f=2 (x)
    if (lane == 3) ob[3] = make_float4(n1[1], n1[2], n1[3], n1[0]); // i=1,f=0 (ebar)
    if (lane == 4) ob[4] = make_float4(n3[1], n3[2], n3[3], n3[0]); // i=1,f=1 (xbar)
    if (lane == 5) ob[5] = make_float4(n3[1], n3[2], n3[3], n3[0]); // i=1,f=2 (xbar)
    if (lane == 6) out[(size_t)B * 24 + b] = growth;
}

extern "C" void kernel_launch(void* const* d_in, const int* in_sizes, int n_in,
                              void* d_out, int out_size) {
    const float* F4  = (const float*)d_in[0];
    const float* ddx = (const float*)d_in[1];
    const float* ddy = (const float*)d_in[2];
    const float* ddz = (const float*)d_in[3];
    const float* dqw = (const float*)d_in[4];
    float* out = (float*)d_out;

    int B  = in_sizes[0] / 24;
    int nd = in_sizes[1];

    int grid = (B + WARPS_PER_BLOCK - 1) / WARPS_PER_BLOCK;
    closure_kernel<<<grid, NTHREADS>>>(F4, ddx, ddy, ddz, dqw, out, B, nd);
}

// round 4
// speedup vs baseline: 1.6005x; 1.2286x over previous
#include <cuda_runtime.h>
#include <cuda_bf16.h>

#define WARPS_PER_BLOCK 8
#define NTHREADS (WARPS_PER_BLOCK * 32)
#define NDIR_MAX 800

__device__ __forceinline__ float fex2(float x){ float r; asm("ex2.approx.f32 %0,%1;" : "=f"(r) : "f"(x)); return r; }
__device__ __forceinline__ float flg2(float x){ float r; asm("lg2.approx.f32 %0,%1;" : "=f"(r) : "f"(x)); return r; }
__device__ __forceinline__ float frcp(float x){ float r; asm("rcp.approx.f32 %0,%1;" : "=f"(r) : "f"(x)); return r; }

__global__ __launch_bounds__(NTHREADS)
void closure_kernel(const float* __restrict__ F4,
                    const float* __restrict__ gdx,
                    const float* __restrict__ gdy,
                    const float* __restrict__ gdz,
                    const float* __restrict__ gqw,
                    float* __restrict__ out,
                    int B, int nd)
{
    // paired path: dirs 0..399 have exact antipodes 400..799 with equal weight
    __shared__ float4 s_dir[NDIR_MAX];               // (dx,dy,dz, log2(w))
    __shared__ float  wred[WARPS_PER_BLOCK][12 * 33];
    const bool paired = (nd == 800);
    const int ntab = paired ? 400 : nd;
    for (int j = threadIdx.x; j < ntab; j += NTHREADS)
        s_dir[j] = make_float4(gdx[j], gdy[j], gdz[j], flg2(gqw[j]));
    __syncthreads();

    const int warp = threadIdx.x >> 5;
    const int lane = threadIdx.x & 31;
    const int b = blockIdx.x * WARPS_PER_BLOCK + warp;
    if (b >= B) return;

    const float EPS    = 1e-12f;
    const float INV4PI = 0.07957747154594767f;
    const float LOG2E  = 1.4426950408889634f;

    const float* in = F4 + (size_t)b * 24;

    // species: 0=e, 1=ebar, 2=x, 3=xbar
    float Fx[4], Fy[4], Fz[4], Ns[4];
    Fx[0] = in[0];  Fy[0] = in[1];  Fz[0] = in[2];  Ns[0] = in[3];
    Fx[1] = in[12]; Fy[1] = in[13]; Fz[1] = in[14]; Ns[1] = in[15];
    Fx[2] = 0.5f*(in[4]  + in[8]);  Fy[2] = 0.5f*(in[5]  + in[9]);
    Fz[2] = 0.5f*(in[6]  + in[10]); Ns[2] = 0.5f*(in[7]  + in[11]);
    Fx[3] = 0.5f*(in[16] + in[20]); Fy[3] = 0.5f*(in[17] + in[21]);
    Fz[3] = 0.5f*(in[18] + in[22]); Ns[3] = 0.5f*(in[19] + in[23]);

    float La[4], Kx[4], Ky[4], Kz[4];
    #pragma unroll
    for (int s = 0; s < 4; s++) {
        float N   = fmaxf(Ns[s], EPS);
        float ss  = Fx[s]*Fx[s] + Fy[s]*Fy[s] + Fz[s]*Fz[s];
        float rs  = rsqrtf(fmaxf(ss, 1e-30f));   // 1/nrm
        float nrm = ss * rs;
        float f   = fminf(fmaxf(nrm * frcp(N), 0.0f), 0.999999f);
        float f2 = f*f, f4 = f2*f2, f6 = f4*f2, f8 = f4*f4;
        float denom = 3.0f - 1.00651f*f2 - 0.962251f*f4 + 1.47353f*f6 - 0.48953f*f8;
        float p = 1.0f - 2.0f*(1.0f - f)*(1.0f + 1.01524f*f) * frcp(fmaxf(denom, EPS));
        float Z = 2.0f*f * frcp(fmaxf(1.0f - p, 1e-6f));
        Z = fminf(Z, 85.0f);
        float zsz;
        if (fabsf(Z) < 1e-4f) {
            float z2 = Z*Z;
            zsz = 1.0f - z2*(1.0f/6.0f) + z2*z2*(1.0f/120.0f);
        } else {
            float E  = fex2(Z * LOG2E);
            float Em = fex2(-Z * LOG2E);
            zsz = Z * frcp(0.5f * (E - Em));
        }
        float A = N * INV4PI * zsz;              // A > 0
        La[s] = flg2(A);
        float scl = Z * LOG2E * rs;
        Kx[s] = Fx[s]*scl; Ky[s] = Fy[s]*scl; Kz[s] = Fz[s]*scl;
    }

    // acc[4s+k]: totals of (w*g_s)*{1,dx,dy,dz};
    // acc[16+k]: sum over {delta>=0} of w*u*{...}; acc[20+k]: same for w*v
    float acc[24];
    #pragma unroll
    for (int i = 0; i < 24; i++) acc[i] = 0.0f;

    if (paired) {
        #pragma unroll 4
        for (int pr = lane; pr < 400; pr += 32) {
            float4 q = s_dir[pr];
            float lw = q.w;
            float gp[4], gm[4];
            #pragma unroll
            for (int s = 0; s < 4; s++) {
                float t = fmaf(Kx[s], q.x, fmaf(Ky[s], q.y, Kz[s]*q.z));
                float c = La[s] + lw;            // fold weight into exponent
                gp[s] = fex2(c + t);             // w*g at +d
                gm[s] = fex2(c - t);             // w*g at -d
                float sm = gp[s] + gm[s];
                float df = gp[s] - gm[s];
                acc[4*s+0] += sm;
                acc[4*s+1] = fmaf(df, q.x, acc[4*s+1]);
                acc[4*s+2] = fmaf(df, q.y, acc[4*s+2]);
                acc[4*s+3] = fmaf(df, q.z, acc[4*s+3]);
            }
            // positive-delta buckets, +d member
            float up = gp[0] - gp[2], vp = gp[1] - gp[3];
            if (up >= vp) {
                acc[16] += up; acc[17] = fmaf(up, q.x, acc[17]); acc[18] = fmaf(up, q.y, acc[18]); acc[19] = fmaf(up, q.z, acc[19]);
                acc[20] += vp; acc[21] = fmaf(vp, q.x, acc[21]); acc[22] = fmaf(vp, q.y, acc[22]); acc[23] = fmaf(vp, q.z, acc[23]);
            }
            // -d member (moments with negated direction)
            float um = gm[0] - gm[2], vm = gm[1] - gm[3];
            if (um >= vm) {
                acc[16] += um; acc[17] = fmaf(um, -q.x, acc[17]); acc[18] = fmaf(um, -q.y, acc[18]); acc[19] = fmaf(um, -q.z, acc[19]);
                acc[20] += vm; acc[21] = fmaf(vm, -q.x, acc[21]); acc[22] = fmaf(vm, -q.y, acc[22]); acc[23] = fmaf(vm, -q.z, acc[23]);
            }
        }
    } else {
        for (int d = lane; d < nd; d += 32) {
            float4 q = s_dir[d];
            float lw = q.w;
            float g[4];
            #pragma unroll
            for (int s = 0; s < 4; s++) {
                float t = fmaf(Kx[s], q.x, fmaf(Ky[s], q.y, Kz[s]*q.z));
                g[s] = fex2(t + La[s] + lw);
                acc[4*s+0] += g[s];
                acc[4*s+1] = fmaf(g[s], q.x, acc[4*s+1]);
                acc[4*s+2] = fmaf(g[s], q.y, acc[4*s+2]);
                acc[4*s+3] = fmaf(g[s], q.z, acc[4*s+3]);
            }
            float wu = g[0] - g[2], wv = g[1] - g[3];
            if (wu >= wv) {
                acc[16] += wu; acc[17] = fmaf(wu, q.x, acc[17]); acc[18] = fmaf(wu, q.y, acc[18]); acc[19] = fmaf(wu, q.z, acc[19]);
                acc[20] += wv; acc[21] = fmaf(wv, q.x, acc[21]); acc[22] = fmaf(wv, q.y, acc[22]); acc[23] = fmaf(wv, q.z, acc[23]);
            }
        }
    }

    // warp reduction via SMEM transpose (2 passes of 12), then shfl broadcast
    float* wr = wred[warp];
    float tot0 = 0.0f, tot1 = 0.0f;
    #pragma unroll
    for (int i = 0; i < 12; i++) wr[i*33 + lane] = acc[i];
    __syncwarp();
    if (lane < 12) {
        float p0 = 0.f, p1 = 0.f, p2 = 0.f, p3 = 0.f;
        const float* row = wr + lane*33;
        #pragma unroll
        for (int j = 0; j < 32; j += 4) { p0 += row[j]; p1 += row[j+1]; p2 += row[j+2]; p3 += row[j+3]; }
        tot0 = (p0 + p1) + (p2 + p3);
    }
    __syncwarp();
    #pragma unroll
    for (int i = 0; i < 12; i++) wr[i*33 + lane] = acc[12 + i];
    __syncwarp();
    if (lane < 12) {
        float p0 = 0.f, p1 = 0.f, p2 = 0.f, p3 = 0.f;
        const float* row = wr + lane*33;
        #pragma unroll
        for (int j = 0; j < 32; j += 4) { p0 += row[j]; p1 += row[j+1]; p2 += row[j+2]; p3 += row[j+3]; }
        tot1 = (p0 + p1) + (p2 + p3);
    }
    float r[24];
    #pragma unroll
    for (int k = 0; k < 12; k++) r[k]      = __shfl_sync(0xffffffffu, tot0, k);
    #pragma unroll
    for (int k = 0; k < 12; k++) r[12 + k] = __shfl_sync(0xffffffffu, tot1, k);

    float Su[4], Sv[4];
    #pragma unroll
    for (int k = 0; k < 4; k++) {
        Su[k] = r[0 + k] - r[8 + k];   // total sum w*u*{1,x,y,z}
        Sv[k] = r[4 + k] - r[12 + k];  // total sum w*v*{1,x,y,z}
    }
    float Iplus  = r[16] - r[20];
    float Iminus = (Sv[0] - r[20]) - (Su[0] - r[16]);
    float Ips = fmaxf(Iplus,  EPS);
    float Ims = fmaxf(Iminus, EPS);
    float cp, cn;
    if (Iplus < Iminus) {
        cp = 1.0f / 3.0f;
        cn = fminf(fmaxf(1.0f - (2.0f/3.0f)*(Ips/Ims), 0.0f), 1.0f);
    } else {
        cn = 1.0f / 3.0f;
        cp = fminf(fmaxf(1.0f - (2.0f/3.0f)*(Ims/Ips), 0.0f), 1.0f);
    }
    float growth = sqrtf(fmaxf(Iplus * Iminus, 0.0f));

    float n0[4], n1[4], n2[4], n3[4];
    #pragma unroll
    for (int k = 0; k < 4; k++) {
        float Pu = cp*r[16 + k] + cn*(Su[k] - r[16 + k]);  // sum w*Psur*u
        float Pv = cp*r[20 + k] + cn*(Sv[k] - r[20 + k]);  // sum w*Psur*v
        n0[k] = r[8 + k]  + Pu;                            // e
        n1[k] = r[12 + k] + Pv;                            // ebar
        n2[k] = 0.5f*(r[0 + k] + r[8 + k])  - 0.5f*Pu;     // x
        n3[k] = 0.5f*(r[4 + k] + r[12 + k]) - 0.5f*Pv;     // xbar
    }

    // F4mix layout (B,2,3,4): channel order [Fx,Fy,Fz,N]
    float4* ob = (float4*)(out + (size_t)b * 24);
    if (lane == 0) ob[0] = make_float4(n0[1], n0[2], n0[3], n0[0]); // i=0,f=0 (e)
    if (lane == 1) ob[1] = make_float4(n2[1], n2[2], n2[3], n2[0]); // i=0,f=1 (x)
    if (lane == 2) ob[2] = make_float4(n2[1], n2[2], n2[3], n2[0]); // i=0,f=2 (x)
    if (lane == 3) ob[3] = make_float4(n1[1], n1[2], n1[3], n1[0]); // i=1,f=0 (ebar)
    if (lane == 4) ob[4] = make_float4(n3[1], n3[2], n3[3], n3[0]); // i=1,f=1 (xbar)
    if (lane == 5) ob[5] = make_float4(n3[1], n3[2], n3[3], n3[0]); // i=1,f=2 (xbar)
    if (lane == 6) out[(size_t)B * 24 + b] = growth;
}

extern "C" void kernel_launch(void* const* d_in, const int* in_sizes, int n_in,
                              void* d_out, int out_size) {
    const float* F4  = (const float*)d_in[0];
    const float* ddx = (const float*)d_in[1];
    const float* ddy = (const float*)d_in[2];
    const float* ddz = (const float*)d_in[3];
    const float* dqw = (const float*)d_in[4];
    float* out = (float*)d_out;

    int B  = in_sizes[0] / 24;
    int nd = in_sizes[1];

    int grid = (B + WARPS_PER_BLOCK - 1) / WARPS_PER_BLOCK;
    closure_kernel<<<grid, NTHREADS>>>(F4, ddx, ddy, ddz, dqw, out, B, nd);
}